// round 1
// baseline (speedup 1.0000x reference)
#include <cuda_runtime.h>
#include <math.h>

// ---------------- model constants ----------------
#define Lc   12
#define Hc   768
#define NHc  12
#define DNc  32
#define DRc  32
#define DVc  64
#define Rc   512
#define Ec   8
#define KTOP 2
#define Ic   256
#define SIc  1024
#define Bc   2
#define Sc   512
#define Tc   (Bc*Sc)          // 1024 tokens
#define QD   (DNc+DRc)        // 64
#define KVD  (DNc+DVc)        // 96
#define KVAW (Rc+DRc)         // 544

// ---------------- scratch (device globals, no allocation) ----------------
__device__ float g_h   [Tc*Hc];
__device__ float g_x   [Tc*Hc];
__device__ float g_q   [Tc*(NHc*QD)];     // 1024x768
__device__ float g_kva [Tc*KVAW];         // 1024x544
__device__ float g_ckv [Tc*Rc];           // 1024x512
__device__ float g_kv  [Tc*(NHc*KVD)];    // 1024x1152
__device__ float g_attn[Tc*Hc];
__device__ float g_t1  [Tc*SIc];
__device__ float g_t3  [Tc*SIc];
__device__ int   g_topi[Tc*KTOP];
__device__ float g_topw[Tc*KTOP];

// ---------------- helpers ----------------
__device__ __forceinline__ float warpsum(float v) {
    #pragma unroll
    for (int o = 16; o; o >>= 1) v += __shfl_down_sync(0xffffffffu, v, o);
    return v;
}

// ---------------- generic GEMM: C(M,N) = A(M,K) @ B(N,K)^T (+bias)(+=) ----------------
#define BM 64
#define BN 64
#define BKK 16

__global__ void gemm_kernel(const float* __restrict__ A, const float* __restrict__ Bw,
                            const float* __restrict__ bias, float* __restrict__ C,
                            int M, int N, int Kd, int accum)
{
    __shared__ float As[BKK][BM];
    __shared__ float Bs[BKK][BN];

    int tid = threadIdx.x;                  // 256
    int tx = tid & 15, ty = tid >> 4;
    int row0 = blockIdx.y * BM;
    int col0 = blockIdx.x * BN;

    float acc[4][4] = {};
    int ntiles = Kd / BKK;

    for (int kt = 0; kt < ntiles; kt++) {
        #pragma unroll
        for (int e = 0; e < 4; e++) {
            int idx = tid + e * 256;
            int m = idx >> 4, k = idx & 15;
            As[k][m] = A[(size_t)(row0 + m) * Kd + kt * BKK + k];
        }
        #pragma unroll
        for (int e = 0; e < 4; e++) {
            int idx = tid + e * 256;
            int n = idx >> 4, k = idx & 15;
            int gn = col0 + n;
            Bs[k][n] = (gn < N) ? Bw[(size_t)gn * Kd + kt * BKK + k] : 0.f;
        }
        __syncthreads();
        #pragma unroll
        for (int k = 0; k < BKK; k++) {
            float4 a4 = *(const float4*)&As[k][ty * 4];
            float4 b4 = *(const float4*)&Bs[k][tx * 4];
            float av[4] = {a4.x, a4.y, a4.z, a4.w};
            float bv[4] = {b4.x, b4.y, b4.z, b4.w};
            #pragma unroll
            for (int i = 0; i < 4; i++)
                #pragma unroll
                for (int j = 0; j < 4; j++)
                    acc[i][j] += av[i] * bv[j];
        }
        __syncthreads();
    }

    #pragma unroll
    for (int i = 0; i < 4; i++) {
        int m = row0 + ty * 4 + i;
        #pragma unroll
        for (int j = 0; j < 4; j++) {
            int n = col0 + tx * 4 + j;
            if (n < N) {
                float v = acc[i][j];
                if (bias) v += bias[n];
                size_t o = (size_t)m * N + n;
                if (accum) C[o] += v; else C[o] = v;
            }
        }
    }
}

// ---------------- RMSNorm (row-wise) ----------------
__global__ void rms_kernel(const float* __restrict__ in, int instride,
                           const float* __restrict__ w,
                           float* __restrict__ out, int outstride, int n)
{
    int t = blockIdx.x, tid = threadIdx.x;
    const float* row = in + (size_t)t * instride;
    __shared__ float sred[256];
    float ss = 0.f;
    for (int j = tid; j < n; j += 256) { float v = row[j]; ss += v * v; }
    sred[tid] = ss; __syncthreads();
    for (int o = 128; o; o >>= 1) { if (tid < o) sred[tid] += sred[tid + o]; __syncthreads(); }
    float inv = rsqrtf(sred[0] / n + 1e-6f);
    float* orow = out + (size_t)t * outstride;
    for (int j = tid; j < n; j += 256) orow[j] = row[j] * inv * w[j];
}

// ---------------- RoPE on q_pe (12 heads) and k_pe (in kva) ----------------
__global__ void rope_kernel()
{
    int t = blockIdx.x;
    int pos = t % Sc;
    int tid = threadIdx.x;           // 256 threads, 13 vectors x 16 pairs = 208 used
    int vec = tid >> 4, i = tid & 15;
    if (vec >= NHc + 1) return;
    float* base = (vec < NHc) ? &g_q[(size_t)t * (NHc * QD) + vec * QD + DNc]
                              : &g_kva[(size_t)t * KVAW + Rc];
    int j1 = i, j2 = i + 16;
    float f1 = powf(10000.0f, -(float)(2 * j1) / 64.0f);
    float f2 = powf(10000.0f, -(float)(2 * j2) / 64.0f);
    float s1, c1, s2, c2;
    sincosf(pos * f1, &s1, &c1);
    sincosf(pos * f2, &s2, &c2);
    float x1 = base[j1], x2 = base[j2];
    base[j1] = x1 * c1 - x2 * s1;   // rot_half[j1] = -x[j1+16]
    base[j2] = x2 * c2 + x1 * s2;   // rot_half[j2] =  x[j2-16]
}

// ---------------- attention: one block per (q,h,b), online row softmax ----------------
__global__ void attn_kernel()
{
    int qpos = blockIdx.x, hId = blockIdx.y, b = blockIdx.z;
    int t = b * Sc + qpos;
    int tid = threadIdx.x;           // 128
    __shared__ float qs[QD];
    __shared__ float sc[Sc];
    __shared__ float rbuf[128];
    __shared__ float obuf[128];

    if (tid < QD) qs[tid] = g_q[(size_t)t * (NHc * QD) + hId * QD + tid];
    __syncthreads();

    int nk = qpos + 1;
    float lmax = -1e30f;
    for (int k = tid; k < nk; k += 128) {
        const float* kn = &g_kv [(size_t)(b * Sc + k) * (NHc * KVD) + hId * KVD];
        const float* kp = &g_kva[(size_t)(b * Sc + k) * KVAW + Rc];
        float s = 0.f;
        #pragma unroll
        for (int i = 0; i < DNc; i++) s += qs[i] * kn[i];
        #pragma unroll
        for (int i = 0; i < DRc; i++) s += qs[DNc + i] * kp[i];
        s *= 0.125f;
        sc[k] = s;
        lmax = fmaxf(lmax, s);
    }
    rbuf[tid] = lmax; __syncthreads();
    for (int o = 64; o; o >>= 1) { if (tid < o) rbuf[tid] = fmaxf(rbuf[tid], rbuf[tid + o]); __syncthreads(); }
    float m = rbuf[0];

    float lsum = 0.f;
    for (int k = tid; k < nk; k += 128) { float e = __expf(sc[k] - m); sc[k] = e; lsum += e; }
    __syncthreads();
    rbuf[tid] = lsum; __syncthreads();
    for (int o = 64; o; o >>= 1) { if (tid < o) rbuf[tid] += rbuf[tid + o]; __syncthreads(); }
    float inv = 1.f / rbuf[0];

    int d = tid & 63, half = tid >> 6;
    float acc = 0.f;
    for (int k = half; k < nk; k += 2)
        acc += sc[k] * g_kv[(size_t)(b * Sc + k) * (NHc * KVD) + hId * KVD + DNc + d];
    obuf[tid] = acc; __syncthreads();
    if (tid < 64)
        g_attn[(size_t)t * Hc + hId * DVc + tid] = (obuf[tid] + obuf[tid + 64]) * inv;
}

// ---------------- gating: softmax over 8 experts, top-2 ----------------
__global__ void gate_kernel(const float* __restrict__ gw)
{
    int t = blockIdx.x, tid = threadIdx.x;   // 256 = 8 warps
    int w = tid >> 5, lane = tid & 31;
    const float* xrow = &g_x[(size_t)t * Hc];
    const float* grow = gw + (size_t)w * Hc;
    float s = 0.f;
    for (int k = lane; k < Hc; k += 32) s += xrow[k] * grow[k];
    s = warpsum(s);
    __shared__ float logit[Ec];
    if (lane == 0) logit[w] = s;
    __syncthreads();
    if (tid == 0) {
        float mx = -1e30f;
        for (int e = 0; e < Ec; e++) mx = fmaxf(mx, logit[e]);
        float ex[Ec];
        for (int e = 0; e < Ec; e++) ex[e] = expf(logit[e] - mx);
        int i0 = 0;
        for (int e = 1; e < Ec; e++) if (ex[e] > ex[i0]) i0 = e;
        int i1 = (i0 == 0) ? 1 : 0;
        for (int e = 0; e < Ec; e++) if (e != i0 && ex[e] > ex[i1]) i1 = e;
        float p0 = ex[i0], p1 = ex[i1], tsum = p0 + p1;
        g_topi[t * 2] = i0; g_topi[t * 2 + 1] = i1;
        g_topw[t * 2] = p0 / tsum; g_topw[t * 2 + 1] = p1 / tsum;
    }
}

// ---------------- sparse MoE: per token, 2 experts, warp-GEMV; h += y ----------------
__global__ void moe_kernel(const float* __restrict__ w1, const float* __restrict__ w2,
                           const float* __restrict__ w3)
{
    int t = blockIdx.x, tid = threadIdx.x;   // 256 = 8 warps
    int warp = tid >> 5, lane = tid & 31;
    __shared__ float xs[Hc];
    __shared__ float gs[Ic];
    __shared__ float ys[Hc];
    for (int j = tid; j < Hc; j += 256) { xs[j] = g_x[(size_t)t * Hc + j]; ys[j] = 0.f; }
    __syncthreads();

    for (int slot = 0; slot < KTOP; slot++) {
        int e = g_topi[t * 2 + slot];
        float wgt = g_topw[t * 2 + slot];
        const float* w1e = w1 + (size_t)e * Ic * Hc;
        const float* w3e = w3 + (size_t)e * Ic * Hc;
        for (int i = warp * 32; i < warp * 32 + 32; i++) {
            const float* r1 = w1e + (size_t)i * Hc;
            const float* r3 = w3e + (size_t)i * Hc;
            float s1 = 0.f, s3 = 0.f;
            for (int k = lane; k < Hc; k += 32) { float xv = xs[k]; s1 += r1[k] * xv; s3 += r3[k] * xv; }
            s1 = warpsum(s1); s3 = warpsum(s3);
            if (lane == 0) gs[i] = (s1 / (1.f + expf(-s1))) * s3;
        }
        __syncthreads();
        const float* w2e = w2 + (size_t)e * Hc * Ic;
        for (int hh = warp; hh < Hc; hh += 8) {
            const float* r2 = w2e + (size_t)hh * Ic;
            float s = 0.f;
            for (int k = lane; k < Ic; k += 32) s += r2[k] * gs[k];
            s = warpsum(s);
            if (lane == 0) ys[hh] += wgt * s;
        }
        __syncthreads();
    }
    for (int j = tid; j < Hc; j += 256) g_h[(size_t)t * Hc + j] += ys[j];
}

// ---------------- elementwise: t1 = silu(t1) * t3 ----------------
__global__ void silu_mul_kernel(int n)
{
    int i = blockIdx.x * blockDim.x + threadIdx.x;
    if (i < n) {
        float a = g_t1[i];
        g_t1[i] = (a / (1.f + expf(-a))) * g_t3[i];
    }
}

// ---------------- final: rms(last token) @ head_w + head_b ----------------
__global__ void final_kernel(const float* __restrict__ fw, const float* __restrict__ hw,
                             const float* __restrict__ hb, float* __restrict__ out)
{
    int b = blockIdx.x, tid = threadIdx.x;   // 256
    int t = b * Sc + (Sc - 1);
    const float* row = &g_h[(size_t)t * Hc];
    __shared__ float sred[256];
    float ss = 0.f;
    for (int j = tid; j < Hc; j += 256) { float v = row[j]; ss += v * v; }
    sred[tid] = ss; __syncthreads();
    for (int o = 128; o; o >>= 1) { if (tid < o) sred[tid] += sred[tid + o]; __syncthreads(); }
    float inv = rsqrtf(sred[0] / Hc + 1e-6f);
    __syncthreads();
    float acc = 0.f;
    for (int j = tid; j < Hc; j += 256) acc += row[j] * inv * fw[j] * hw[j];
    sred[tid] = acc; __syncthreads();
    for (int o = 128; o; o >>= 1) { if (tid < o) sred[tid] += sred[tid + o]; __syncthreads(); }
    if (tid == 0) out[b] = sred[0] + hb[0];
}

// ---------------- launch ----------------
static inline void gemm(const float* A, const float* Bw, const float* bias, float* C,
                        int M, int N, int Kd, int accum)
{
    dim3 grid((N + BN - 1) / BN, M / BM);
    gemm_kernel<<<grid, 256>>>(A, Bw, bias, C, M, N, Kd, accum);
}

extern "C" void kernel_launch(void* const* d_in, const int* in_sizes, int n_in,
                              void* d_out, int out_size)
{
    const float* inputs   = (const float*)d_in[0];
    const float* in_w     = (const float*)d_in[1];
    const float* in_b     = (const float*)d_in[2];
    const float* attn_nw  = (const float*)d_in[3];
    const float* wq       = (const float*)d_in[4];
    const float* wkva     = (const float*)d_in[5];
    const float* kvn_w    = (const float*)d_in[6];
    const float* wkvb     = (const float*)d_in[7];
    const float* wo       = (const float*)d_in[8];
    const float* moe_nw   = (const float*)d_in[9];
    const float* gate_w   = (const float*)d_in[10];
    const float* e_w1     = (const float*)d_in[11];
    const float* e_w2     = (const float*)d_in[12];
    const float* e_w3     = (const float*)d_in[13];
    const float* s_w1     = (const float*)d_in[14];
    const float* s_w2     = (const float*)d_in[15];
    const float* s_w3     = (const float*)d_in[16];
    const float* final_nw = (const float*)d_in[17];
    const float* head_w   = (const float*)d_in[18];
    const float* head_b   = (const float*)d_in[19];
    float* out = (float*)d_out;

    float *h_p, *x_p, *q_p, *kva_p, *ckv_p, *kv_p, *attn_p, *t1_p, *t3_p;
    cudaGetSymbolAddress((void**)&h_p,    g_h);
    cudaGetSymbolAddress((void**)&x_p,    g_x);
    cudaGetSymbolAddress((void**)&q_p,    g_q);
    cudaGetSymbolAddress((void**)&kva_p,  g_kva);
    cudaGetSymbolAddress((void**)&ckv_p,  g_ckv);
    cudaGetSymbolAddress((void**)&kv_p,   g_kv);
    cudaGetSymbolAddress((void**)&attn_p, g_attn);
    cudaGetSymbolAddress((void**)&t1_p,   g_t1);
    cudaGetSymbolAddress((void**)&t3_p,   g_t3);

    // embed: h = inputs @ in_w^T + in_b    (1024x768, K=64)
    gemm(inputs, in_w, in_b, h_p, Tc, Hc, 64, 0);

    for (int l = 0; l < Lc; l++) {
        const float* anw   = attn_nw + (size_t)l * Hc;
        const float* wq_l  = wq      + (size_t)l * Hc * Hc;
        const float* wva_l = wkva    + (size_t)l * KVAW * Hc;
        const float* kvn_l = kvn_w   + (size_t)l * Rc;
        const float* wvb_l = wkvb    + (size_t)l * (NHc * KVD) * Rc;
        const float* wo_l  = wo      + (size_t)l * Hc * Hc;
        const float* mnw   = moe_nw  + (size_t)l * Hc;
        const float* gw_l  = gate_w  + (size_t)l * Ec * Hc;
        const float* w1_l  = e_w1    + (size_t)l * Ec * Ic * Hc;
        const float* w2_l  = e_w2    + (size_t)l * Ec * Hc * Ic;
        const float* w3_l  = e_w3    + (size_t)l * Ec * Ic * Hc;
        const float* sw1_l = s_w1    + (size_t)l * SIc * Hc;
        const float* sw2_l = s_w2    + (size_t)l * Hc * SIc;
        const float* sw3_l = s_w3    + (size_t)l * SIc * Hc;

        // attention
        rms_kernel<<<Tc, 256>>>(h_p, Hc, anw, x_p, Hc, Hc);
        gemm(x_p, wq_l,  nullptr, q_p,   Tc, Hc,        Hc, 0);
        gemm(x_p, wva_l, nullptr, kva_p, Tc, KVAW,      Hc, 0);
        rope_kernel<<<Tc, 256>>>();
        rms_kernel<<<Tc, 256>>>(kva_p, KVAW, kvn_l, ckv_p, Rc, Rc);
        gemm(ckv_p, wvb_l, nullptr, kv_p, Tc, NHc * KVD, Rc, 0);
        {
            dim3 grid(Sc, NHc, Bc);
            attn_kernel<<<grid, 128>>>();
        }
        gemm(attn_p, wo_l, nullptr, h_p, Tc, Hc, Hc, 1);   // h += attn @ wo^T

        // MoE
        rms_kernel<<<Tc, 256>>>(h_p, Hc, mnw, x_p, Hc, Hc);
        gate_kernel<<<Tc, 256>>>(gw_l);
        moe_kernel<<<Tc, 256>>>(w1_l, w2_l, w3_l);          // h += sparse expert out
        gemm(x_p, sw1_l, nullptr, t1_p, Tc, SIc, Hc, 0);
        gemm(x_p, sw3_l, nullptr, t3_p, Tc, SIc, Hc, 0);
        silu_mul_kernel<<<(Tc * SIc) / 256, 256>>>(Tc * SIc);
        gemm(t1_p, sw2_l, nullptr, h_p, Tc, Hc, SIc, 1);    // h += g @ sw2^T
    }

    final_kernel<<<Bc, 256>>>(final_nw, head_w, head_b, out);
}

// round 2
// speedup vs baseline: 3.2869x; 3.2869x over previous
#include <cuda_runtime.h>
#include <math.h>

// ---------------- model constants ----------------
#define Lc   12
#define Hc   768
#define NHc  12
#define DNc  32
#define DRc  32
#define DVc  64
#define Rc   512
#define Ec   8
#define KTOP 2
#define Ic   256
#define SIc  1024
#define Bc   2
#define Sc   512
#define Tc   (Bc*Sc)          // 1024 tokens
#define QD   (DNc+DRc)        // 64
#define KVD  (DNc+DVc)        // 96
#define KVAW (Rc+DRc)         // 544

// ---------------- scratch (device globals, no allocation) ----------------
__device__ float g_h   [Tc*Hc];
__device__ float g_x   [Tc*Hc];
__device__ float g_q   [Tc*(NHc*QD)];
__device__ float g_kva [Tc*KVAW];
__device__ float g_ckv [Tc*Rc];
__device__ float g_kv  [Tc*(NHc*KVD)];
__device__ float g_attn[Tc*Hc];
__device__ float g_t1  [Tc*SIc];
__device__ float g_t3  [Tc*SIc];
__device__ float g_mg  [Ec*Tc*Ic];       // gathered expert gate outputs
__device__ float g_eo  [Tc*2*Hc];        // per (token,slot) expert outputs
__device__ int   g_list[Ec*Tc];          // per-expert token2slot lists
__device__ int   g_cnt [Ec];
__device__ float g_topw[Tc*KTOP];

// ---------------- helpers ----------------
__device__ __forceinline__ float warpsum(float v) {
    #pragma unroll
    for (int o = 16; o; o >>= 1) v += __shfl_down_sync(0xffffffffu, v, o);
    return v;
}

// ---------------- generic GEMM: C(M,N) = A(M,K) @ B(N,K)^T (+bias)(+=) ----------------
#define BM 64
#define BN 64
#define BK 16
#define LDA 68   // 64 + 4 pad (keeps float4 alignment, kills 16-way conflicts)

__global__ __launch_bounds__(256, 2) void gemm_kernel(
    const float* __restrict__ A, const float* __restrict__ Bw,
    const float* __restrict__ bias, float* __restrict__ C,
    int M, int N, int Kd, int accum)
{
    __shared__ float As[2][BK][LDA];
    __shared__ float Bs[2][BK][LDA];

    int tid = threadIdx.x;
    int tx = tid & 15, ty = tid >> 4;
    int row0 = blockIdx.y * BM, col0 = blockIdx.x * BN;

    int lm = tid >> 2;            // 0..63
    int lk = (tid & 3) * 4;       // 0,4,8,12

    const float* Ap = A + (size_t)(row0 + lm) * Kd + lk;
    int gn = col0 + lm;
    const float* Bp = Bw + (size_t)gn * Kd + lk;
    bool bok = gn < N;

    int nt = Kd / BK;
    float4 ra, rb;

    // prologue: tile 0 -> smem[0], tile 1 -> regs
    ra = *(const float4*)Ap;
    rb = bok ? *(const float4*)Bp : make_float4(0.f,0.f,0.f,0.f);
    #pragma unroll
    for (int j = 0; j < 4; j++) {
        As[0][lk + j][lm] = ((float*)&ra)[j];
        Bs[0][lk + j][lm] = ((float*)&rb)[j];
    }
    ra = *(const float4*)(Ap + BK);
    rb = bok ? *(const float4*)(Bp + BK) : make_float4(0.f,0.f,0.f,0.f);
    __syncthreads();

    float acc[4][4] = {};
    for (int kt = 0; kt < nt; kt++) {
        int buf = kt & 1;
        if (kt + 1 < nt) {
            #pragma unroll
            for (int j = 0; j < 4; j++) {
                As[buf ^ 1][lk + j][lm] = ((float*)&ra)[j];
                Bs[buf ^ 1][lk + j][lm] = ((float*)&rb)[j];
            }
        }
        if (kt + 2 < nt) {
            ra = *(const float4*)(Ap + (kt + 2) * BK);
            rb = bok ? *(const float4*)(Bp + (kt + 2) * BK) : make_float4(0.f,0.f,0.f,0.f);
        }
        #pragma unroll
        for (int k = 0; k < BK; k++) {
            float4 a4 = *(const float4*)&As[buf][k][ty * 4];
            float4 b4 = *(const float4*)&Bs[buf][k][tx * 4];
            float av[4] = {a4.x, a4.y, a4.z, a4.w};
            float bv[4] = {b4.x, b4.y, b4.z, b4.w};
            #pragma unroll
            for (int i = 0; i < 4; i++)
                #pragma unroll
                for (int j = 0; j < 4; j++)
                    acc[i][j] += av[i] * bv[j];
        }
        __syncthreads();
    }

    #pragma unroll
    for (int i = 0; i < 4; i++) {
        int m = row0 + ty * 4 + i;
        #pragma unroll
        for (int j = 0; j < 4; j++) {
            int n = col0 + tx * 4 + j;
            if (n < N) {
                float v = acc[i][j];
                if (bias) v += bias[n];
                size_t o = (size_t)m * N + n;
                if (accum) C[o] += v; else C[o] = v;
            }
        }
    }
}

// ---------------- RMSNorm (row-wise) ----------------
__global__ void rms_kernel(const float* __restrict__ in, int instride,
                           const float* __restrict__ w,
                           float* __restrict__ out, int outstride, int n)
{
    int t = blockIdx.x, tid = threadIdx.x;
    const float* row = in + (size_t)t * instride;
    __shared__ float sred[256];
    float ss = 0.f;
    for (int j = tid; j < n; j += 256) { float v = row[j]; ss += v * v; }
    sred[tid] = ss; __syncthreads();
    for (int o = 128; o; o >>= 1) { if (tid < o) sred[tid] += sred[tid + o]; __syncthreads(); }
    float inv = rsqrtf(sred[0] / n + 1e-6f);
    float* orow = out + (size_t)t * outstride;
    for (int j = tid; j < n; j += 256) orow[j] = row[j] * inv * w[j];
}

// ---------------- RoPE on q_pe (12 heads) and k_pe ----------------
__global__ void rope_kernel()
{
    int t = blockIdx.x;
    int pos = t % Sc;
    int tid = threadIdx.x;
    int vec = tid >> 4, i = tid & 15;
    if (vec >= NHc + 1) return;
    float* base = (vec < NHc) ? &g_q[(size_t)t * (NHc * QD) + vec * QD + DNc]
                              : &g_kva[(size_t)t * KVAW + Rc];
    int j1 = i, j2 = i + 16;
    float f1 = powf(10000.0f, -(float)(2 * j1) / 64.0f);
    float f2 = powf(10000.0f, -(float)(2 * j2) / 64.0f);
    float s1, c1, s2, c2;
    sincosf(pos * f1, &s1, &c1);
    sincosf(pos * f2, &s2, &c2);
    float x1 = base[j1], x2 = base[j2];
    base[j1] = x1 * c1 - x2 * s1;
    base[j2] = x2 * c2 + x1 * s2;
}

// ---------------- flash attention: block per (qtile64, head, batch) ----------------
#define ALD 68
__global__ __launch_bounds__(256) void attn_kernel()
{
    int qt  = (int)gridDim.x - 1 - (int)blockIdx.x;   // big tiles first
    int hId = blockIdx.y, b = blockIdx.z;
    int tid = threadIdx.x;
    int tx = tid & 15, ty = tid >> 4;
    int lr = tid >> 2, sub = tid & 3;   // loader mapping

    extern __shared__ float sm[];
    float* qsT = sm;                 // [64 d][68]
    float* ksT = sm + 64 * ALD;      // [64 d][68]
    float* vs  = sm + 2 * 64 * ALD;  // [64 k][68]
    float* ps  = sm + 3 * 64 * ALD;  // [64 q][68]

    int q0 = qt * 64;

    // load q tile transposed: qsT[d][row]
    {
        const float* qrow = &g_q[(size_t)(b * Sc + q0 + lr) * (NHc * QD) + hId * QD];
        #pragma unroll
        for (int i = 0; i < 16; i++) {
            int d = sub * 16 + i;
            qsT[d * ALD + lr] = qrow[d];
        }
    }

    float m[4], l[4], acc[4][4];
    #pragma unroll
    for (int i = 0; i < 4; i++) {
        m[i] = -1e30f; l[i] = 0.f;
        #pragma unroll
        for (int j = 0; j < 4; j++) acc[i][j] = 0.f;
    }

    for (int kt = 0; kt <= qt; kt++) {
        __syncthreads();   // prev iter done with ks/vs/ps
        {
            int kg = b * Sc + kt * 64 + lr;
            const float* kn = &g_kv [(size_t)kg * (NHc * KVD) + hId * KVD];
            const float* kp = &g_kva[(size_t)kg * KVAW + Rc];
            #pragma unroll
            for (int i = 0; i < 8; i++) {
                int d = sub * 8 + i;
                ksT[d * ALD + lr]        = kn[d];
                ksT[(32 + d) * ALD + lr] = kp[d];
            }
            const float* vp = kn + DNc;
            #pragma unroll
            for (int i = 0; i < 4; i++)
                *(float4*)&vs[lr * ALD + sub * 16 + i * 4] = *(const float4*)(vp + sub * 16 + i * 4);
        }
        __syncthreads();

        // scores S[ty*4+i][tx*4+j]
        float s[4][4] = {};
        #pragma unroll
        for (int d = 0; d < 64; d++) {
            float4 a4 = *(const float4*)&qsT[d * ALD + ty * 4];
            float4 b4 = *(const float4*)&ksT[d * ALD + tx * 4];
            float av[4] = {a4.x, a4.y, a4.z, a4.w};
            float bv[4] = {b4.x, b4.y, b4.z, b4.w};
            #pragma unroll
            for (int i = 0; i < 4; i++)
                #pragma unroll
                for (int j = 0; j < 4; j++)
                    s[i][j] += av[i] * bv[j];
        }
        #pragma unroll
        for (int i = 0; i < 4; i++)
            #pragma unroll
            for (int j = 0; j < 4; j++) {
                float v = s[i][j] * 0.125f;
                if (kt == qt && (tx * 4 + j) > (ty * 4 + i)) v = -1e30f;
                s[i][j] = v;
            }

        // online softmax per row (rows ty*4+i, reduce over 16 tx lanes)
        #pragma unroll
        for (int i = 0; i < 4; i++) {
            float mx = fmaxf(fmaxf(s[i][0], s[i][1]), fmaxf(s[i][2], s[i][3]));
            #pragma unroll
            for (int o = 1; o < 16; o <<= 1) mx = fmaxf(mx, __shfl_xor_sync(0xffffffffu, mx, o));
            float mn = fmaxf(m[i], mx);
            float alpha = __expf(m[i] - mn);
            float sum = 0.f;
            #pragma unroll
            for (int j = 0; j < 4; j++) { float p = __expf(s[i][j] - mn); s[i][j] = p; sum += p; }
            #pragma unroll
            for (int o = 1; o < 16; o <<= 1) sum += __shfl_xor_sync(0xffffffffu, sum, o);
            l[i] = l[i] * alpha + sum;
            m[i] = mn;
            #pragma unroll
            for (int j = 0; j < 4; j++) acc[i][j] *= alpha;
            #pragma unroll
            for (int j = 0; j < 4; j++) ps[(ty * 4 + i) * ALD + tx * 4 + j] = s[i][j];
        }
        __syncthreads();

        // PV: acc[i][jj] += sum_j ps[row][j] * vs[j][tx*4+jj]
        #pragma unroll 8
        for (int j = 0; j < 64; j++) {
            float4 b4 = *(const float4*)&vs[j * ALD + tx * 4];
            float bv[4] = {b4.x, b4.y, b4.z, b4.w};
            #pragma unroll
            for (int i = 0; i < 4; i++) {
                float a = ps[(ty * 4 + i) * ALD + j];
                #pragma unroll
                for (int jj = 0; jj < 4; jj++) acc[i][jj] += a * bv[jj];
            }
        }
    }

    #pragma unroll
    for (int i = 0; i < 4; i++) {
        float inv = 1.f / l[i];
        int t = b * Sc + q0 + ty * 4 + i;
        #pragma unroll
        for (int jj = 0; jj < 4; jj++)
            g_attn[(size_t)t * Hc + hId * DVc + tx * 4 + jj] = acc[i][jj] * inv;
    }
}

// ---------------- gating: softmax over 8 experts, top-2, build expert lists ----------------
__global__ void zero_cnt_kernel() { if (threadIdx.x < Ec) g_cnt[threadIdx.x] = 0; }

__global__ void gate_kernel(const float* __restrict__ gw)
{
    int t = blockIdx.x, tid = threadIdx.x;
    int w = tid >> 5, lane = tid & 31;
    const float* xrow = &g_x[(size_t)t * Hc];
    const float* grow = gw + (size_t)w * Hc;
    float s = 0.f;
    for (int k = lane; k < Hc; k += 32) s += xrow[k] * grow[k];
    s = warpsum(s);
    __shared__ float logit[Ec];
    if (lane == 0) logit[w] = s;
    __syncthreads();
    if (tid == 0) {
        float mx = -1e30f;
        for (int e = 0; e < Ec; e++) mx = fmaxf(mx, logit[e]);
        float ex[Ec];
        for (int e = 0; e < Ec; e++) ex[e] = expf(logit[e] - mx);
        int i0 = 0;
        for (int e = 1; e < Ec; e++) if (ex[e] > ex[i0]) i0 = e;
        int i1 = (i0 == 0) ? 1 : 0;
        for (int e = 0; e < Ec; e++) if (e != i0 && ex[e] > ex[i1]) i1 = e;
        float p0 = ex[i0], p1 = ex[i1], tsum = p0 + p1;
        g_topw[t * 2]     = p0 / tsum;
        g_topw[t * 2 + 1] = p1 / tsum;
        int pos0 = atomicAdd(&g_cnt[i0], 1);
        g_list[i0 * Tc + pos0] = t * 2;
        int pos1 = atomicAdd(&g_cnt[i1], 1);
        g_list[i1 * Tc + pos1] = t * 2 + 1;
    }
}

// ---------------- MoE stage 1: g = silu(x@w1^T)*(x@w3^T), gathered rows ----------------
__global__ __launch_bounds__(256) void moe_mlp1_kernel(const float* __restrict__ w1,
                                                       const float* __restrict__ w3)
{
    int e = blockIdx.z;
    int cnt = g_cnt[e];
    int row0 = blockIdx.y * BM;
    if (row0 >= cnt) return;
    int col0 = blockIdx.x * BN;

    __shared__ float As [2][BK][LDA];
    __shared__ float B1s[2][BK][LDA];
    __shared__ float B3s[2][BK][LDA];

    int tid = threadIdx.x;
    int tx = tid & 15, ty = tid >> 4;
    int lm = tid >> 2, lk = (tid & 3) * 4;

    int grow = row0 + lm;
    bool aok = grow < cnt;
    int tok2 = aok ? g_list[e * Tc + grow] : 0;
    const float* Ap  = &g_x[(size_t)(tok2 >> 1) * Hc + lk];
    const float* B1p = w1 + ((size_t)e * Ic + col0 + lm) * Hc + lk;
    const float* B3p = w3 + ((size_t)e * Ic + col0 + lm) * Hc + lk;

    int nt = Hc / BK;
    float4 ra, r1, r3;
    ra = aok ? *(const float4*)Ap : make_float4(0.f,0.f,0.f,0.f);
    r1 = *(const float4*)B1p;
    r3 = *(const float4*)B3p;
    #pragma unroll
    for (int j = 0; j < 4; j++) {
        As [0][lk + j][lm] = ((float*)&ra)[j];
        B1s[0][lk + j][lm] = ((float*)&r1)[j];
        B3s[0][lk + j][lm] = ((float*)&r3)[j];
    }
    ra = aok ? *(const float4*)(Ap + BK) : make_float4(0.f,0.f,0.f,0.f);
    r1 = *(const float4*)(B1p + BK);
    r3 = *(const float4*)(B3p + BK);
    __syncthreads();

    float a1[4][4] = {}, a3[4][4] = {};
    for (int kt = 0; kt < nt; kt++) {
        int buf = kt & 1;
        if (kt + 1 < nt) {
            #pragma unroll
            for (int j = 0; j < 4; j++) {
                As [buf ^ 1][lk + j][lm] = ((float*)&ra)[j];
                B1s[buf ^ 1][lk + j][lm] = ((float*)&r1)[j];
                B3s[buf ^ 1][lk + j][lm] = ((float*)&r3)[j];
            }
        }
        if (kt + 2 < nt) {
            ra = aok ? *(const float4*)(Ap + (kt + 2) * BK) : make_float4(0.f,0.f,0.f,0.f);
            r1 = *(const float4*)(B1p + (kt + 2) * BK);
            r3 = *(const float4*)(B3p + (kt + 2) * BK);
        }
        #pragma unroll
        for (int k = 0; k < BK; k++) {
            float4 a4 = *(const float4*)&As [buf][k][ty * 4];
            float4 b1 = *(const float4*)&B1s[buf][k][tx * 4];
            float4 b3 = *(const float4*)&B3s[buf][k][tx * 4];
            float av[4] = {a4.x, a4.y, a4.z, a4.w};
            float v1[4] = {b1.x, b1.y, b1.z, b1.w};
            float v3[4] = {b3.x, b3.y, b3.z, b3.w};
            #pragma unroll
            for (int i = 0; i < 4; i++)
                #pragma unroll
                for (int j = 0; j < 4; j++) {
                    a1[i][j] += av[i] * v1[j];
                    a3[i][j] += av[i] * v3[j];
                }
        }
        __syncthreads();
    }

    #pragma unroll
    for (int i = 0; i < 4; i++) {
        int r = row0 + ty * 4 + i;
        if (r < cnt) {
            float* orow = &g_mg[((size_t)e * Tc + r) * Ic + col0];
            #pragma unroll
            for (int j = 0; j < 4; j++) {
                float a = a1[i][j];
                orow[tx * 4 + j] = (a / (1.f + __expf(-a))) * a3[i][j];
            }
        }
    }
}

// ---------------- MoE stage 2: eo[(t,slot)] = wgt * (g @ w2^T) ----------------
__global__ __launch_bounds__(256) void moe_mlp2_kernel(const float* __restrict__ w2)
{
    int e = blockIdx.z;
    int cnt = g_cnt[e];
    int row0 = blockIdx.y * BM;
    if (row0 >= cnt) return;
    int col0 = blockIdx.x * BN;

    __shared__ float As[2][BK][LDA];
    __shared__ float Bs[2][BK][LDA];

    int tid = threadIdx.x;
    int tx = tid & 15, ty = tid >> 4;
    int lm = tid >> 2, lk = (tid & 3) * 4;

    const float* Ap = &g_mg[((size_t)e * Tc + row0 + lm) * Ic + lk];
    const float* Bp = w2 + ((size_t)e * Hc + col0 + lm) * Ic + lk;

    int nt = Ic / BK;
    float4 ra, rb;
    ra = *(const float4*)Ap;
    rb = *(const float4*)Bp;
    #pragma unroll
    for (int j = 0; j < 4; j++) {
        As[0][lk + j][lm] = ((float*)&ra)[j];
        Bs[0][lk + j][lm] = ((float*)&rb)[j];
    }
    ra = *(const float4*)(Ap + BK);
    rb = *(const float4*)(Bp + BK);
    __syncthreads();

    float acc[4][4] = {};
    for (int kt = 0; kt < nt; kt++) {
        int buf = kt & 1;
        if (kt + 1 < nt) {
            #pragma unroll
            for (int j = 0; j < 4; j++) {
                As[buf ^ 1][lk + j][lm] = ((float*)&ra)[j];
                Bs[buf ^ 1][lk + j][lm] = ((float*)&rb)[j];
            }
        }
        if (kt + 2 < nt) {
            ra = *(const float4*)(Ap + (kt + 2) * BK);
            rb = *(const float4*)(Bp + (kt + 2) * BK);
        }
        #pragma unroll
        for (int k = 0; k < BK; k++) {
            float4 a4 = *(const float4*)&As[buf][k][ty * 4];
            float4 b4 = *(const float4*)&Bs[buf][k][tx * 4];
            float av[4] = {a4.x, a4.y, a4.z, a4.w};
            float bv[4] = {b4.x, b4.y, b4.z, b4.w};
            #pragma unroll
            for (int i = 0; i < 4; i++)
                #pragma unroll
                for (int j = 0; j < 4; j++)
                    acc[i][j] += av[i] * bv[j];
        }
        __syncthreads();
    }

    #pragma unroll
    for (int i = 0; i < 4; i++) {
        int r = row0 + ty * 4 + i;
        if (r < cnt) {
            int tok2 = g_list[e * Tc + r];
            float wgt = g_topw[tok2];
            float* orow = &g_eo[(size_t)tok2 * Hc + col0];
            #pragma unroll
            for (int j = 0; j < 4; j++)
                orow[tx * 4 + j] = wgt * acc[i][j];
        }
    }
}

// ---------------- combine: h += eo[slot0] + eo[slot1] ----------------
__global__ void combine_kernel()
{
    int i = blockIdx.x * 256 + threadIdx.x;   // over Tc*Hc
    int t = i / Hc, j = i - t * Hc;
    g_h[i] += g_eo[(size_t)(t * 2) * Hc + j] + g_eo[(size_t)(t * 2 + 1) * Hc + j];
}

// ---------------- elementwise: t1 = silu(t1) * t3 ----------------
__global__ void silu_mul_kernel(int n)
{
    int i = blockIdx.x * blockDim.x + threadIdx.x;
    if (i < n) {
        float a = g_t1[i];
        g_t1[i] = (a / (1.f + expf(-a))) * g_t3[i];
    }
}

// ---------------- final: rms(last token) @ head_w + head_b ----------------
__global__ void final_kernel(const float* __restrict__ fw, const float* __restrict__ hw,
                             const float* __restrict__ hb, float* __restrict__ out)
{
    int b = blockIdx.x, tid = threadIdx.x;
    int t = b * Sc + (Sc - 1);
    const float* row = &g_h[(size_t)t * Hc];
    __shared__ float sred[256];
    float ss = 0.f;
    for (int j = tid; j < Hc; j += 256) { float v = row[j]; ss += v * v; }
    sred[tid] = ss; __syncthreads();
    for (int o = 128; o; o >>= 1) { if (tid < o) sred[tid] += sred[tid + o]; __syncthreads(); }
    float inv = rsqrtf(sred[0] / Hc + 1e-6f);
    __syncthreads();
    float acc = 0.f;
    for (int j = tid; j < Hc; j += 256) acc += row[j] * inv * fw[j] * hw[j];
    sred[tid] = acc; __syncthreads();
    for (int o = 128; o; o >>= 1) { if (tid < o) sred[tid] += sred[tid + o]; __syncthreads(); }
    if (tid == 0) out[b] = sred[0] + hb[0];
}

// ---------------- launch ----------------
static inline void gemm(const float* A, const float* Bw, const float* bias, float* C,
                        int M, int N, int Kd, int accum)
{
    dim3 grid((N + BN - 1) / BN, M / BM);
    gemm_kernel<<<grid, 256>>>(A, Bw, bias, C, M, N, Kd, accum);
}

extern "C" void kernel_launch(void* const* d_in, const int* in_sizes, int n_in,
                              void* d_out, int out_size)
{
    const float* inputs   = (const float*)d_in[0];
    const float* in_w     = (const float*)d_in[1];
    const float* in_b     = (const float*)d_in[2];
    const float* attn_nw  = (const float*)d_in[3];
    const float* wq       = (const float*)d_in[4];
    const float* wkva     = (const float*)d_in[5];
    const float* kvn_w    = (const float*)d_in[6];
    const float* wkvb     = (const float*)d_in[7];
    const float* wo       = (const float*)d_in[8];
    const float* moe_nw   = (const float*)d_in[9];
    const float* gate_w   = (const float*)d_in[10];
    const float* e_w1     = (const float*)d_in[11];
    const float* e_w2     = (const float*)d_in[12];
    const float* e_w3     = (const float*)d_in[13];
    const float* s_w1     = (const float*)d_in[14];
    const float* s_w2     = (const float*)d_in[15];
    const float* s_w3     = (const float*)d_in[16];
    const float* final_nw = (const float*)d_in[17];
    const float* head_w   = (const float*)d_in[18];
    const float* head_b   = (const float*)d_in[19];
    float* out = (float*)d_out;

    float *h_p, *x_p, *q_p, *kva_p, *ckv_p, *kv_p, *attn_p, *t1_p, *t3_p;
    cudaGetSymbolAddress((void**)&h_p,    g_h);
    cudaGetSymbolAddress((void**)&x_p,    g_x);
    cudaGetSymbolAddress((void**)&q_p,    g_q);
    cudaGetSymbolAddress((void**)&kva_p,  g_kva);
    cudaGetSymbolAddress((void**)&ckv_p,  g_ckv);
    cudaGetSymbolAddress((void**)&kv_p,   g_kv);
    cudaGetSymbolAddress((void**)&attn_p, g_attn);
    cudaGetSymbolAddress((void**)&t1_p,   g_t1);
    cudaGetSymbolAddress((void**)&t3_p,   g_t3);

    const int attn_smem = 4 * 64 * ALD * sizeof(float);   // 69632 B
    cudaFuncSetAttribute(attn_kernel, cudaFuncAttributeMaxDynamicSharedMemorySize, attn_smem);

    // embed: h = inputs @ in_w^T + in_b
    gemm(inputs, in_w, in_b, h_p, Tc, Hc, 64, 0);

    for (int l = 0; l < Lc; l++) {
        const float* anw   = attn_nw + (size_t)l * Hc;
        const float* wq_l  = wq      + (size_t)l * Hc * Hc;
        const float* wva_l = wkva    + (size_t)l * KVAW * Hc;
        const float* kvn_l = kvn_w   + (size_t)l * Rc;
        const float* wvb_l = wkvb    + (size_t)l * (NHc * KVD) * Rc;
        const float* wo_l  = wo      + (size_t)l * Hc * Hc;
        const float* mnw   = moe_nw  + (size_t)l * Hc;
        const float* gw_l  = gate_w  + (size_t)l * Ec * Hc;
        const float* w1_l  = e_w1    + (size_t)l * Ec * Ic * Hc;
        const float* w2_l  = e_w2    + (size_t)l * Ec * Hc * Ic;
        const float* w3_l  = e_w3    + (size_t)l * Ec * Ic * Hc;
        const float* sw1_l = s_w1    + (size_t)l * SIc * Hc;
        const float* sw2_l = s_w2    + (size_t)l * Hc * SIc;
        const float* sw3_l = s_w3    + (size_t)l * SIc * Hc;

        // attention
        rms_kernel<<<Tc, 256>>>(h_p, Hc, anw, x_p, Hc, Hc);
        gemm(x_p, wq_l,  nullptr, q_p,   Tc, Hc,   Hc, 0);
        gemm(x_p, wva_l, nullptr, kva_p, Tc, KVAW, Hc, 0);
        rope_kernel<<<Tc, 256>>>();
        rms_kernel<<<Tc, 256>>>(kva_p, KVAW, kvn_l, ckv_p, Rc, Rc);
        gemm(ckv_p, wvb_l, nullptr, kv_p, Tc, NHc * KVD, Rc, 0);
        {
            dim3 grid(Sc / 64, NHc, Bc);
            attn_kernel<<<grid, 256, attn_smem>>>();
        }
        gemm(attn_p, wo_l, nullptr, h_p, Tc, Hc, Hc, 1);

        // MoE
        rms_kernel<<<Tc, 256>>>(h_p, Hc, mnw, x_p, Hc, Hc);
        zero_cnt_kernel<<<1, 32>>>();
        gate_kernel<<<Tc, 256>>>(gw_l);
        {
            dim3 g1(Ic / BN, Tc / BM, Ec);
            moe_mlp1_kernel<<<g1, 256>>>(w1_l, w3_l);
            dim3 g2(Hc / BN, Tc / BM, Ec);
            moe_mlp2_kernel<<<g2, 256>>>(w2_l);
            combine_kernel<<<(Tc * Hc) / 256, 256>>>();
        }
        gemm(x_p, sw1_l, nullptr, t1_p, Tc, SIc, Hc, 0);
        gemm(x_p, sw3_l, nullptr, t3_p, Tc, SIc, Hc, 0);
        silu_mul_kernel<<<(Tc * SIc) / 256, 256>>>(Tc * SIc);
        gemm(t1_p, sw2_l, nullptr, h_p, Tc, Hc, SIc, 1);
    }

    final_kernel<<<Bc, 256>>>(final_nw, head_w, head_b, out);
}